// round 13
// baseline (speedup 1.0000x reference)
#include <cuda_runtime.h>
#include <cstdint>

#define N_NODES 50000
#define N_EDGES 500000
#define SD 128
#define VD 3
#define HID 64
#define DEPTH 4
#define CUTOFF 5.0f

#define EBLK 192

// ---------------- scratch state ----------------
__device__ float g_s[N_NODES * SD];
__device__ float g_v[N_NODES * VD * 3];
__device__ float g_zagg[N_NODES * HID];    // scatter of z = C * (h2 @ Wz)
__device__ float g_vagg[N_NODES * VD * 3];
__device__ float g_cnt[N_NODES];
__device__ float g_inv[N_NODES];
__device__ float g_sumC[N_NODES];
__device__ float g_C[N_EDGES];
__device__ float g_ha[N_NODES * HID];      // s @ W1[0:128] + b1
__device__ float g_hb[N_NODES * HID];      // s @ W1[128:256]
__device__ float g_Wz[DEPTH * HID * HID];  // W3s @ Wn1b (all layers)
__device__ float g_bz[DEPTH * HID];        // b3s @ Wn1b

__device__ __forceinline__ float silu(float x) {
    return x / (1.0f + __expf(-x));
}

// ---------------- packed f32x2 helpers ----------------
__device__ __forceinline__ unsigned long long pack2(float x) {
    unsigned long long p;
    unsigned int u = __float_as_uint(x);
    asm("mov.b64 %0, {%1, %1};" : "=l"(p) : "r"(u));
    return p;
}
__device__ __forceinline__ void unpack2(unsigned long long p, float& lo, float& hi) {
    unsigned int a, b;
    asm("mov.b64 {%0, %1}, %2;" : "=r"(a), "=r"(b) : "l"(p));
    lo = __uint_as_float(a);
    hi = __uint_as_float(b);
}
__device__ __forceinline__ void fma2(unsigned long long& acc,
                                     unsigned long long a, unsigned long long b) {
    asm("fma.rn.f32x2 %0, %1, %2, %0;" : "+l"(acc) : "l"(a), "l"(b));
}
__device__ __forceinline__ unsigned long long mul2(unsigned long long a,
                                                   unsigned long long b) {
    unsigned long long d;
    asm("mul.rn.f32x2 %0, %1, %2;" : "=l"(d) : "l"(a), "l"(b));
    return d;
}

__device__ __forceinline__ void red_add4(float* p, float a, float b, float c, float d) {
    asm volatile("red.global.add.v4.f32 [%0], {%1,%2,%3,%4};"
                 :: "l"(p), "f"(a), "f"(b), "f"(c), "f"(d) : "memory");
}
__device__ __forceinline__ void red_add1(float* p, float a) {
    asm volatile("red.global.add.f32 [%0], %1;" :: "l"(p), "f"(a) : "memory");
}

// ---------------- prep kernels ----------------
__global__ void init_state(const float* __restrict__ s, const float* __restrict__ v) {
    int i = blockIdx.x * blockDim.x + threadIdx.x;
    int stride = gridDim.x * blockDim.x;
    for (int k = i; k < N_NODES * SD; k += stride) g_s[k] = s[k];
    for (int k = i; k < N_NODES * VD * 3; k += stride) g_v[k] = v[k];
    for (int k = i; k < N_NODES; k += stride) { g_cnt[k] = 0.0f; g_sumC[k] = 0.0f; }
}

__global__ void prep_edges(const int* __restrict__ ei, const float* __restrict__ d) {
    int e = blockIdx.x * blockDim.x + threadIdx.x;
    if (e >= N_EDGES) return;
    int dst = ei[e];
    float dd = d[e];
    float c = 0.5f * (cospif(dd * (1.0f / CUTOFF)) + 1.0f);
    c = (dd < CUTOFF) ? c : 0.0f;
    g_C[e] = c;
    red_add1(&g_cnt[dst], 1.0f);
    red_add1(&g_sumC[dst], c);
}

__global__ void compute_inv() {
    int n = blockIdx.x * blockDim.x + threadIdx.x;
    if (n < N_NODES) g_inv[n] = 1.0f / fmaxf(g_cnt[n], 1.0f);
}

__global__ void zero_agg() {
    int i = blockIdx.x * blockDim.x + threadIdx.x;
    int stride = gridDim.x * blockDim.x;
    for (int k = i; k < N_NODES * HID; k += stride) g_zagg[k] = 0.0f;
    for (int k = i; k < N_NODES * VD * 3; k += stride) g_vagg[k] = 0.0f;
}

// ---------------- all-layer weight fold: Wz = W3s @ Wn1b, bz = b3s @ Wn1b ----
__global__ void fuse_w3_all(const float* __restrict__ W3, const float* __restrict__ Wn1,
                            const float* __restrict__ b3) {
    int idx = blockIdx.x * 256 + threadIdx.x;
    const int per_layer = HID * HID + HID;
    int layer = idx / per_layer;
    if (layer >= DEPTH) return;
    int li = idx - layer * per_layer;
    const float* W3g = W3 + (size_t)layer * HID * 134;
    const float* Wb  = Wn1 + (size_t)layer * 2 * SD * HID + SD * HID; // rows 128..255
    if (li < HID * HID) {
        int k = li >> 6, n = li & 63;
        float acc = 0.0f;
        for (int j = 0; j < SD; j++) acc += W3g[k * 134 + j] * Wb[j * HID + n];
        g_Wz[layer * HID * HID + li] = acc;
    } else {
        int n = li - HID * HID;
        const float* b3g = b3 + layer * 134;
        float acc = 0.0f;
        for (int j = 0; j < SD; j++) acc += b3g[j] * Wb[j * HID + n];
        g_bz[layer * HID + n] = acc;
    }
}

// ---------------- per-node W1 precompute (128-thread blocks for occupancy) --
__global__ __launch_bounds__(128) void precompute_h(
    const float* __restrict__ W1, const float* __restrict__ b1, int layer)
{
    extern __shared__ float sm[];
    float* W1s = sm;              // 256*64
    float* b1s = W1s + 256 * HID; // 64

    const float* W1g = W1 + (size_t)layer * 257 * HID;
    for (int i = threadIdx.x; i < 256 * HID; i += 128) W1s[i] = W1g[i];
    if (threadIdx.x < HID) b1s[threadIdx.x] = b1[layer * HID + threadIdx.x];
    __syncthreads();

    int n = blockIdx.x * 128 + threadIdx.x;
    if (n >= N_NODES) return;

    const float4* xs = reinterpret_cast<const float4*>(g_s + (size_t)n * SD);

    // ---- ha ----
    unsigned long long acc[32];
    {
        const unsigned long long* bp = (const unsigned long long*)b1s;
#pragma unroll
        for (int q = 0; q < 32; q++) acc[q] = bp[q];
    }
#pragma unroll 4
    for (int kk = 0; kk < SD / 4; kk++) {
        float4 xv = xs[kk];
        float xr[4] = {xv.x, xv.y, xv.z, xv.w};
#pragma unroll
        for (int t = 0; t < 4; t++) {
            unsigned long long xk2 = pack2(xr[t]);
            const ulonglong2* wrow = reinterpret_cast<const ulonglong2*>(W1s + (kk * 4 + t) * HID);
#pragma unroll
            for (int q = 0; q < 16; q++) {
                ulonglong2 w = wrow[q];
                fma2(acc[2 * q + 0], xk2, w.x);
                fma2(acc[2 * q + 1], xk2, w.y);
            }
        }
    }
    {
        float* hap = g_ha + (size_t)n * HID;
#pragma unroll
        for (int q = 0; q < 32; q++) {
            float lo, hi;
            unpack2(acc[q], lo, hi);
            hap[2 * q + 0] = lo;
            hap[2 * q + 1] = hi;
        }
    }

    // ---- hb ----
#pragma unroll
    for (int q = 0; q < 32; q++) acc[q] = 0ULL;
#pragma unroll 4
    for (int kk = 0; kk < SD / 4; kk++) {
        float4 xv = xs[kk];
        float xr[4] = {xv.x, xv.y, xv.z, xv.w};
#pragma unroll
        for (int t = 0; t < 4; t++) {
            unsigned long long xk2 = pack2(xr[t]);
            const ulonglong2* wrow = reinterpret_cast<const ulonglong2*>(W1s + (SD + kk * 4 + t) * HID);
#pragma unroll
            for (int q = 0; q < 16; q++) {
                ulonglong2 w = wrow[q];
                fma2(acc[2 * q + 0], xk2, w.x);
                fma2(acc[2 * q + 1], xk2, w.y);
            }
        }
    }
    {
        float* hbp = g_hb + (size_t)n * HID;
#pragma unroll
        for (int q = 0; q < 32; q++) {
            float lo, hi;
            unpack2(acc[q], lo, hi);
            hbp[2 * q + 0] = lo;
            hbp[2 * q + 1] = hi;
        }
    }
}

// ---------------- fused edge MLP + scatter (192 thr, 170-reg cap, 1-pass) ---
__global__ __launch_bounds__(EBLK, 2) void edge_kernel(
    const int* __restrict__ ei, const float* __restrict__ d, const float* __restrict__ r,
    const float* __restrict__ W1, const float* __restrict__ W2,
    const float* __restrict__ b2, const float* __restrict__ W3,
    const float* __restrict__ b3, int layer)
{
    extern __shared__ float sm[];
    float* W2s  = sm;                 // 64*64
    float* Wzs  = W2s + HID * HID;    // 64*64
    float* W3vs = Wzs + HID * HID;    // 64*8 (6 used, padded)
    float* wds  = W3vs + HID * 8;     // 64
    float* b2s  = wds + HID;          // 64
    float* b3vs = b2s + HID;          // 8

    const float* W2g = W2 + (size_t)layer * HID * HID;
    const float* W3g = W3 + (size_t)layer * HID * 134;
    const float* b3g = b3 + (size_t)layer * 134;
    const float* wdg = W1 + (size_t)layer * 257 * HID + 256 * HID;
    const float* Wzg = g_Wz + (size_t)layer * HID * HID;

    int tid = threadIdx.x;
    for (int i = tid; i < HID * HID; i += EBLK) { W2s[i] = W2g[i]; Wzs[i] = Wzg[i]; }
    for (int i = tid; i < HID * 6; i += EBLK) {
        int k = i / 6, j = i - k * 6;
        W3vs[k * 8 + j] = W3g[k * 134 + SD + j];
    }
    if (tid < HID) { wds[tid] = wdg[tid]; b2s[tid] = b2[layer * HID + tid]; }
    if (tid < 6) b3vs[tid] = b3g[SD + tid];
    __syncthreads();

    int e = blockIdx.x * EBLK + tid;
    if (e >= N_EDGES) return;

    int dst = ei[e];
    int src = ei[N_EDGES + e];
    float C = g_C[e];
    float de = d[e];

    // ---- h1 = silu(ha[dst] + hb[src] + d*wd) ----
    float h1[HID];
    {
        const float4* ap = reinterpret_cast<const float4*>(g_ha + (size_t)dst * HID);
        const float4* bp = reinterpret_cast<const float4*>(g_hb + (size_t)src * HID);
        const float4* wp = reinterpret_cast<const float4*>(wds);
#pragma unroll
        for (int q = 0; q < HID / 4; q++) {
            float4 a = ap[q], b = bp[q], w = wp[q];
            h1[4 * q + 0] = silu(fmaf(de, w.x, a.x + b.x));
            h1[4 * q + 1] = silu(fmaf(de, w.y, a.y + b.y));
            h1[4 * q + 2] = silu(fmaf(de, w.z, a.z + b.z));
            h1[4 * q + 3] = silu(fmaf(de, w.w, a.w + b.w));
        }
    }

    // ---- h2 = silu(h1 @ W2 + b2), single 64-wide pass ----
    float h2[HID];
    {
        unsigned long long acc[32];
        const unsigned long long* bp = (const unsigned long long*)b2s;
#pragma unroll
        for (int q = 0; q < 32; q++) acc[q] = bp[q];
#pragma unroll 4
        for (int k = 0; k < HID; k++) {
            unsigned long long hk2 = pack2(h1[k]);
            const ulonglong2* wrow = reinterpret_cast<const ulonglong2*>(W2s + k * HID);
#pragma unroll
            for (int q = 0; q < 16; q++) {
                ulonglong2 w = wrow[q];
                fma2(acc[2 * q + 0], hk2, w.x);
                fma2(acc[2 * q + 1], hk2, w.y);
            }
        }
#pragma unroll
        for (int q = 0; q < 32; q++) {
            float lo, hi;
            unpack2(acc[q], lo, hi);
            h2[2 * q + 0] = silu(lo);
            h2[2 * q + 1] = silu(hi);
        }
    }

    // ---- z = h2 @ Wz (single pass) + gv/gr, scatter C*z ----
    unsigned long long C2 = pack2(C);
    float* zbase = g_zagg + (size_t)dst * HID;

    unsigned long long g01 = ((const unsigned long long*)b3vs)[0];
    unsigned long long g23 = ((const unsigned long long*)b3vs)[1];
    unsigned long long g45 = ((const unsigned long long*)b3vs)[2];

    {
        unsigned long long acc[32];
#pragma unroll
        for (int q = 0; q < 32; q++) acc[q] = 0ULL;
#pragma unroll 4
        for (int k = 0; k < HID; k++) {
            unsigned long long hk2 = pack2(h2[k]);
            const ulonglong2* wrow = reinterpret_cast<const ulonglong2*>(Wzs + k * HID);
#pragma unroll
            for (int q = 0; q < 16; q++) {
                ulonglong2 w = wrow[q];
                fma2(acc[2 * q + 0], hk2, w.x);
                fma2(acc[2 * q + 1], hk2, w.y);
            }
            const unsigned long long* gw = (const unsigned long long*)(W3vs + k * 8);
            fma2(g01, hk2, gw[0]);
            fma2(g23, hk2, gw[1]);
            fma2(g45, hk2, gw[2]);
        }
#pragma unroll
        for (int q = 0; q < 16; q++) {
            unsigned long long p0 = mul2(acc[2 * q + 0], C2);
            unsigned long long p1 = mul2(acc[2 * q + 1], C2);
            float a0, a1, a2, a3;
            unpack2(p0, a0, a1);
            unpack2(p1, a2, a3);
            red_add4(zbase + q * 4, a0, a1, a2, a3);
        }
    }

    // ---- vector scatter ----
    float g6[6];
    unpack2(g01, g6[0], g6[1]);
    unpack2(g23, g6[2], g6[3]);
    unpack2(g45, g6[4], g6[5]);

    float rr0 = r[e * 3 + 0], rr1 = r[e * 3 + 1], rr2 = r[e * 3 + 2];
    const float* vs = g_v + (size_t)src * 9;
    float* vdp = g_vagg + (size_t)dst * 9;
#pragma unroll
    for (int a = 0; a < 3; a++) {
        float gva = g6[a] * C, gra = g6[3 + a] * C;
        red_add1(vdp + a * 3 + 0, vs[a * 3 + 0] * gva + rr0 * gra);
        red_add1(vdp + a * 3 + 1, vs[a * 3 + 1] * gva + rr1 * gra);
        red_add1(vdp + a * 3 + 2, vs[a * 3 + 2] * gva + rr2 * gra);
    }
}

// ---------------- fused node MLP + residual (128-thread blocks) -------------
__global__ __launch_bounds__(128) void node_kernel(
    const float* __restrict__ Wn1, const float* __restrict__ bn1,
    const float* __restrict__ Wn2, const float* __restrict__ bn2, int layer)
{
    extern __shared__ float sm[];
    float* W1s = sm;                 // 128*64 (Wn1 rows 0..127 only)
    float* W2s = W1s + SD * HID;     // 64*128
    float* b1s = W2s + HID * SD;     // 64
    float* b2s = b1s + HID;          // 128
    float* bzs = b2s + SD;           // 64

    const float* W1g = Wn1 + (size_t)layer * 2 * SD * HID;   // first 128 rows
    const float* W2g = Wn2 + (size_t)layer * HID * SD;
    for (int i = threadIdx.x; i < SD * HID; i += 128) W1s[i] = W1g[i];
    for (int i = threadIdx.x; i < HID * SD; i += 128) W2s[i] = W2g[i];
    if (threadIdx.x < HID) {
        b1s[threadIdx.x] = bn1[layer * HID + threadIdx.x];
        bzs[threadIdx.x] = g_bz[layer * HID + threadIdx.x];
    }
    if (threadIdx.x < SD) b2s[threadIdx.x] = bn2[layer * SD + threadIdx.x];
    __syncthreads();

    int n = blockIdx.x * 128 + threadIdx.x;
    if (n >= N_NODES) return;

    const float4* xs = reinterpret_cast<const float4*>(g_s + (size_t)n * SD);
    float sumC = g_sumC[n];
    const unsigned long long* zag = (const unsigned long long*)(g_zagg + (size_t)n * HID);

    // ---- u = silu(s@Wn1a + bn1 + zagg + sumC*bz) ----
    unsigned long long up[32];
    {
        const unsigned long long* bp = (const unsigned long long*)b1s;
#pragma unroll
        for (int q = 0; q < 32; q++) up[q] = bp[q];
    }
#pragma unroll 4
    for (int kk = 0; kk < SD / 4; kk++) {
        float4 xv = xs[kk];
        float xr[4] = {xv.x, xv.y, xv.z, xv.w};
#pragma unroll
        for (int t = 0; t < 4; t++) {
            unsigned long long xk2 = pack2(xr[t]);
            const ulonglong2* wrow = reinterpret_cast<const ulonglong2*>(W1s + (kk * 4 + t) * HID);
#pragma unroll
            for (int q = 0; q < 16; q++) {
                ulonglong2 w = wrow[q];
                fma2(up[2 * q + 0], xk2, w.x);
                fma2(up[2 * q + 1], xk2, w.y);
            }
        }
    }
    float u[HID];
#pragma unroll
    for (int q = 0; q < 32; q++) {
        float lo, hi;
        unpack2(up[q], lo, hi);
        float zl, zh;
        unpack2(zag[q], zl, zh);
        u[2 * q + 0] = silu(lo + zl + sumC * bzs[2 * q + 0]);
        u[2 * q + 1] = silu(hi + zh + sumC * bzs[2 * q + 1]);
    }

    float* sp = g_s + (size_t)n * SD;
#pragma unroll 1
    for (int c = 0; c < 4; c++) {
        unsigned long long acc[16];
        const unsigned long long* bp = (const unsigned long long*)(b2s + c * 32);
#pragma unroll
        for (int q = 0; q < 16; q++) acc[q] = bp[q];
#pragma unroll 4
        for (int k = 0; k < HID; k++) {
            unsigned long long hk2 = pack2(u[k]);
            const ulonglong2* wrow = reinterpret_cast<const ulonglong2*>(W2s + k * SD + c * 32);
#pragma unroll
            for (int q = 0; q < 8; q++) {
                ulonglong2 w = wrow[q];
                fma2(acc[2 * q + 0], hk2, w.x);
                fma2(acc[2 * q + 1], hk2, w.y);
            }
        }
#pragma unroll
        for (int q = 0; q < 16; q++) {
            float lo, hi;
            unpack2(acc[q], lo, hi);
            sp[c * 32 + 2 * q + 0] += lo;
            sp[c * 32 + 2 * q + 1] += hi;
        }
    }

    float inv = g_inv[n];
    float* vp = g_v + (size_t)n * 9;
    const float* va = g_vagg + (size_t)n * 9;
#pragma unroll
    for (int i = 0; i < 9; i++) vp[i] += va[i] * inv;
}

__global__ void write_out(float* __restrict__ out) {
    int i = blockIdx.x * blockDim.x + threadIdx.x;
    int stride = gridDim.x * blockDim.x;
    for (int k = i; k < N_NODES * SD; k += stride) out[k] = g_s[k];
    for (int k = i; k < N_NODES * VD * 3; k += stride) out[N_NODES * SD + k] = g_v[k];
}

// ---------------- launch ----------------
extern "C" void kernel_launch(void* const* d_in, const int* in_sizes, int n_in,
                              void* d_out, int out_size) {
    const float* s   = (const float*)d_in[0];
    const float* v   = (const float*)d_in[1];
    const int*   ei  = (const int*)d_in[2];
    const float* d   = (const float*)d_in[3];
    const float* r   = (const float*)d_in[4];
    const float* W1  = (const float*)d_in[5];
    const float* b1  = (const float*)d_in[6];
    const float* W2  = (const float*)d_in[7];
    const float* b2  = (const float*)d_in[8];
    const float* W3  = (const float*)d_in[9];
    const float* b3  = (const float*)d_in[10];
    const float* Wn1 = (const float*)d_in[11];
    const float* bn1 = (const float*)d_in[12];
    const float* Wn2 = (const float*)d_in[13];
    const float* bn2 = (const float*)d_in[14];
    float* out = (float*)d_out;

    const int pre_smem  = (256 * HID + HID) * 4;
    const int edge_smem = (HID * HID * 2 + HID * 8 + HID + HID + 8) * 4;
    const int node_smem = (SD * HID + HID * SD + HID + SD + HID) * 4;
    cudaFuncSetAttribute(precompute_h, cudaFuncAttributeMaxDynamicSharedMemorySize, pre_smem);
    cudaFuncSetAttribute(edge_kernel, cudaFuncAttributeMaxDynamicSharedMemorySize, edge_smem);
    cudaFuncSetAttribute(node_kernel, cudaFuncAttributeMaxDynamicSharedMemorySize, node_smem);

    init_state<<<1024, 256>>>(s, v);
    prep_edges<<<(N_EDGES + 255) / 256, 256>>>(ei, d);
    compute_inv<<<(N_NODES + 255) / 256, 256>>>();
    fuse_w3_all<<<(DEPTH * (HID * HID + HID) + 255) / 256, 256>>>(W3, Wn1, b3);

    for (int l = 0; l < DEPTH; l++) {
        precompute_h<<<(N_NODES + 127) / 128, 128, pre_smem>>>(W1, b1, l);
        zero_agg<<<1024, 256>>>();
        edge_kernel<<<(N_EDGES + EBLK - 1) / EBLK, EBLK, edge_smem>>>(ei, d, r, W1, W2, b2, W3, b3, l);
        node_kernel<<<(N_NODES + 127) / 128, 128, node_smem>>>(Wn1, bn1, Wn2, bn2, l);
    }
    write_out<<<1024, 256>>>(out);
}

// round 15
// speedup vs baseline: 1.0930x; 1.0930x over previous
#include <cuda_runtime.h>
#include <cstdint>

#define N_NODES 50000
#define N_EDGES 500000
#define SD 128
#define VD 3
#define HID 64
#define DEPTH 4
#define CUTOFF 5.0f

#define EBLK 192

// ---------------- scratch state ----------------
__device__ float g_s[N_NODES * SD];
__device__ float g_v[N_NODES * VD * 3];
__device__ float g_h2agg[N_NODES * HID];     // scatter of C * h2 (Wz applied per-node)
__device__ float g_vagg[N_NODES * 12];       // padded: [n*12 + a*4 + j], j<3 used
__device__ float g_cnt[N_NODES];
__device__ float g_inv[N_NODES];
__device__ float g_sumC[N_NODES];
__device__ float g_C[N_EDGES];
__device__ float g_ha[N_NODES * HID];        // s @ W1[0:128] + b1
__device__ float g_hb[N_NODES * HID];        // s @ W1[128:256]
__device__ float g_Wz[DEPTH * HID * HID];    // W3s @ Wn1b (all layers)
__device__ float g_bz[DEPTH * HID];          // b3s @ Wn1b

__device__ __forceinline__ float silu(float x) {
    return x / (1.0f + __expf(-x));
}

// ---------------- packed f32x2 helpers ----------------
__device__ __forceinline__ unsigned long long pack2(float x) {
    unsigned long long p;
    unsigned int u = __float_as_uint(x);
    asm("mov.b64 %0, {%1, %1};" : "=l"(p) : "r"(u));
    return p;
}
__device__ __forceinline__ void unpack2(unsigned long long p, float& lo, float& hi) {
    unsigned int a, b;
    asm("mov.b64 {%0, %1}, %2;" : "=r"(a), "=r"(b) : "l"(p));
    lo = __uint_as_float(a);
    hi = __uint_as_float(b);
}
__device__ __forceinline__ void fma2(unsigned long long& acc,
                                     unsigned long long a, unsigned long long b) {
    asm("fma.rn.f32x2 %0, %1, %2, %0;" : "+l"(acc) : "l"(a), "l"(b));
}

__device__ __forceinline__ void red_add4(float* p, float a, float b, float c, float d) {
    asm volatile("red.global.add.v4.f32 [%0], {%1,%2,%3,%4};"
                 :: "l"(p), "f"(a), "f"(b), "f"(c), "f"(d) : "memory");
}
__device__ __forceinline__ void red_add1(float* p, float a) {
    asm volatile("red.global.add.f32 [%0], %1;" :: "l"(p), "f"(a) : "memory");
}

// ---------------- prep kernels ----------------
__global__ void init_state(const float* __restrict__ s, const float* __restrict__ v) {
    int i = blockIdx.x * blockDim.x + threadIdx.x;
    int stride = gridDim.x * blockDim.x;
    for (int k = i; k < N_NODES * SD; k += stride) g_s[k] = s[k];
    for (int k = i; k < N_NODES * VD * 3; k += stride) g_v[k] = v[k];
    for (int k = i; k < N_NODES; k += stride) { g_cnt[k] = 0.0f; g_sumC[k] = 0.0f; }
}

__global__ void prep_edges(const int* __restrict__ ei, const float* __restrict__ d) {
    int e = blockIdx.x * blockDim.x + threadIdx.x;
    if (e >= N_EDGES) return;
    int dst = ei[e];
    float dd = d[e];
    float c = 0.5f * (cospif(dd * (1.0f / CUTOFF)) + 1.0f);
    c = (dd < CUTOFF) ? c : 0.0f;
    g_C[e] = c;
    red_add1(&g_cnt[dst], 1.0f);
    red_add1(&g_sumC[dst], c);
}

__global__ void compute_inv() {
    int n = blockIdx.x * blockDim.x + threadIdx.x;
    if (n < N_NODES) g_inv[n] = 1.0f / fmaxf(g_cnt[n], 1.0f);
}

__global__ void zero_agg() {
    int i = blockIdx.x * blockDim.x + threadIdx.x;
    int stride = gridDim.x * blockDim.x;
    for (int k = i; k < N_NODES * HID; k += stride) g_h2agg[k] = 0.0f;
    for (int k = i; k < N_NODES * 12; k += stride) g_vagg[k] = 0.0f;
}

// ---------------- all-layer weight fold: Wz = W3s @ Wn1b, bz = b3s @ Wn1b ----
__global__ void fuse_w3_all(const float* __restrict__ W3, const float* __restrict__ Wn1,
                            const float* __restrict__ b3) {
    int idx = blockIdx.x * 256 + threadIdx.x;
    const int per_layer = HID * HID + HID;
    int layer = idx / per_layer;
    if (layer >= DEPTH) return;
    int li = idx - layer * per_layer;
    const float* W3g = W3 + (size_t)layer * HID * 134;
    const float* Wb  = Wn1 + (size_t)layer * 2 * SD * HID + SD * HID; // rows 128..255
    if (li < HID * HID) {
        int k = li >> 6, n = li & 63;
        float acc = 0.0f;
        for (int j = 0; j < SD; j++) acc += W3g[k * 134 + j] * Wb[j * HID + n];
        g_Wz[layer * HID * HID + li] = acc;
    } else {
        int n = li - HID * HID;
        const float* b3g = b3 + layer * 134;
        float acc = 0.0f;
        for (int j = 0; j < SD; j++) acc += b3g[j] * Wb[j * HID + n];
        g_bz[layer * HID + n] = acc;
    }
}

// ---------------- per-node W1 precompute (128-thread blocks for occupancy) --
__global__ __launch_bounds__(128) void precompute_h(
    const float* __restrict__ W1, const float* __restrict__ b1, int layer)
{
    extern __shared__ float sm[];
    float* W1s = sm;              // 256*64
    float* b1s = W1s + 256 * HID; // 64

    const float* W1g = W1 + (size_t)layer * 257 * HID;
    for (int i = threadIdx.x; i < 256 * HID; i += 128) W1s[i] = W1g[i];
    if (threadIdx.x < HID) b1s[threadIdx.x] = b1[layer * HID + threadIdx.x];
    __syncthreads();

    int n = blockIdx.x * 128 + threadIdx.x;
    if (n >= N_NODES) return;

    const float4* xs = reinterpret_cast<const float4*>(g_s + (size_t)n * SD);

    // ---- ha ----
    unsigned long long acc[32];
    {
        const unsigned long long* bp = (const unsigned long long*)b1s;
#pragma unroll
        for (int q = 0; q < 32; q++) acc[q] = bp[q];
    }
#pragma unroll 4
    for (int kk = 0; kk < SD / 4; kk++) {
        float4 xv = xs[kk];
        float xr[4] = {xv.x, xv.y, xv.z, xv.w};
#pragma unroll
        for (int t = 0; t < 4; t++) {
            unsigned long long xk2 = pack2(xr[t]);
            const ulonglong2* wrow = reinterpret_cast<const ulonglong2*>(W1s + (kk * 4 + t) * HID);
#pragma unroll
            for (int q = 0; q < 16; q++) {
                ulonglong2 w = wrow[q];
                fma2(acc[2 * q + 0], xk2, w.x);
                fma2(acc[2 * q + 1], xk2, w.y);
            }
        }
    }
    {
        float* hap = g_ha + (size_t)n * HID;
#pragma unroll
        for (int q = 0; q < 32; q++) {
            float lo, hi;
            unpack2(acc[q], lo, hi);
            hap[2 * q + 0] = lo;
            hap[2 * q + 1] = hi;
        }
    }

    // ---- hb ----
#pragma unroll
    for (int q = 0; q < 32; q++) acc[q] = 0ULL;
#pragma unroll 4
    for (int kk = 0; kk < SD / 4; kk++) {
        float4 xv = xs[kk];
        float xr[4] = {xv.x, xv.y, xv.z, xv.w};
#pragma unroll
        for (int t = 0; t < 4; t++) {
            unsigned long long xk2 = pack2(xr[t]);
            const ulonglong2* wrow = reinterpret_cast<const ulonglong2*>(W1s + (SD + kk * 4 + t) * HID);
#pragma unroll
            for (int q = 0; q < 16; q++) {
                ulonglong2 w = wrow[q];
                fma2(acc[2 * q + 0], xk2, w.x);
                fma2(acc[2 * q + 1], xk2, w.y);
            }
        }
    }
    {
        float* hbp = g_hb + (size_t)n * HID;
#pragma unroll
        for (int q = 0; q < 32; q++) {
            float lo, hi;
            unpack2(acc[q], lo, hi);
            hbp[2 * q + 0] = lo;
            hbp[2 * q + 1] = hi;
        }
    }
}

// ---------------- fused edge MLP + scatter (z-GEMM deferred to node) --------
__global__ __launch_bounds__(EBLK, 2) void edge_kernel(
    const int* __restrict__ ei, const float* __restrict__ d, const float* __restrict__ r,
    const float* __restrict__ W1, const float* __restrict__ W2,
    const float* __restrict__ b2, const float* __restrict__ W3,
    const float* __restrict__ b3, int layer)
{
    extern __shared__ float sm[];
    float* W2s  = sm;                 // 64*64
    float* W3vs = W2s + HID * HID;    // 64*8 (6 used, padded)
    float* wds  = W3vs + HID * 8;     // 64
    float* b2s  = wds + HID;          // 64
    float* b3vs = b2s + HID;          // 8

    const float* W2g = W2 + (size_t)layer * HID * HID;
    const float* W3g = W3 + (size_t)layer * HID * 134;
    const float* b3g = b3 + (size_t)layer * 134;
    const float* wdg = W1 + (size_t)layer * 257 * HID + 256 * HID;

    int tid = threadIdx.x;
    for (int i = tid; i < HID * HID; i += EBLK) W2s[i] = W2g[i];
    for (int i = tid; i < HID * 6; i += EBLK) {
        int k = i / 6, j = i - k * 6;
        W3vs[k * 8 + j] = W3g[k * 134 + SD + j];
    }
    if (tid < HID) { wds[tid] = wdg[tid]; b2s[tid] = b2[layer * HID + tid]; }
    if (tid < 6) b3vs[tid] = b3g[SD + tid];
    __syncthreads();

    int e = blockIdx.x * EBLK + tid;
    if (e >= N_EDGES) return;

    int dst = ei[e];
    int src = ei[N_EDGES + e];
    float C = g_C[e];
    float de = d[e];

    // ---- h1 = silu(ha[dst] + hb[src] + d*wd) ----
    float h1[HID];
    {
        const float4* ap = reinterpret_cast<const float4*>(g_ha + (size_t)dst * HID);
        const float4* bp = reinterpret_cast<const float4*>(g_hb + (size_t)src * HID);
        const float4* wp = reinterpret_cast<const float4*>(wds);
#pragma unroll
        for (int q = 0; q < HID / 4; q++) {
            float4 a = ap[q], b = bp[q], w = wp[q];
            h1[4 * q + 0] = silu(fmaf(de, w.x, a.x + b.x));
            h1[4 * q + 1] = silu(fmaf(de, w.y, a.y + b.y));
            h1[4 * q + 2] = silu(fmaf(de, w.z, a.z + b.z));
            h1[4 * q + 3] = silu(fmaf(de, w.w, a.w + b.w));
        }
    }

    // ---- h2 = silu(h1 @ W2 + b2), single 64-wide pass ----
    float h2[HID];
    {
        unsigned long long acc[32];
        const unsigned long long* bp = (const unsigned long long*)b2s;
#pragma unroll
        for (int q = 0; q < 32; q++) acc[q] = bp[q];
#pragma unroll 4
        for (int k = 0; k < HID; k++) {
            unsigned long long hk2 = pack2(h1[k]);
            const ulonglong2* wrow = reinterpret_cast<const ulonglong2*>(W2s + k * HID);
#pragma unroll
            for (int q = 0; q < 16; q++) {
                ulonglong2 w = wrow[q];
                fma2(acc[2 * q + 0], hk2, w.x);
                fma2(acc[2 * q + 1], hk2, w.y);
            }
        }
#pragma unroll
        for (int q = 0; q < 32; q++) {
            float lo, hi;
            unpack2(acc[q], lo, hi);
            h2[2 * q + 0] = silu(lo);
            h2[2 * q + 1] = silu(hi);
        }
    }

    // ---- scatter C*h2 (Wz applied per-node later) ----
    {
        float* zbase = g_h2agg + (size_t)dst * HID;
#pragma unroll
        for (int q = 0; q < 16; q++) {
            red_add4(zbase + q * 4,
                     C * h2[4 * q + 0], C * h2[4 * q + 1],
                     C * h2[4 * q + 2], C * h2[4 * q + 3]);
        }
    }

    // ---- g6 = h2 @ W3v + b3v (gv/gr columns), vector scatter ----
    unsigned long long g01 = ((const unsigned long long*)b3vs)[0];
    unsigned long long g23 = ((const unsigned long long*)b3vs)[1];
    unsigned long long g45 = ((const unsigned long long*)b3vs)[2];
#pragma unroll 4
    for (int k = 0; k < HID; k++) {
        unsigned long long hk2 = pack2(h2[k]);
        const unsigned long long* gw = (const unsigned long long*)(W3vs + k * 8);
        fma2(g01, hk2, gw[0]);
        fma2(g23, hk2, gw[1]);
        fma2(g45, hk2, gw[2]);
    }
    float g6[6];
    unpack2(g01, g6[0], g6[1]);
    unpack2(g23, g6[2], g6[3]);
    unpack2(g45, g6[4], g6[5]);

    float rr0 = r[e * 3 + 0], rr1 = r[e * 3 + 1], rr2 = r[e * 3 + 2];
    const float* vs = g_v + (size_t)src * 9;
    float* vdp = g_vagg + (size_t)dst * 12;
#pragma unroll
    for (int a = 0; a < 3; a++) {
        float gva = g6[a] * C, gra = g6[3 + a] * C;
        red_add4(vdp + a * 4,
                 vs[a * 3 + 0] * gva + rr0 * gra,
                 vs[a * 3 + 1] * gva + rr1 * gra,
                 vs[a * 3 + 2] * gva + rr2 * gra,
                 0.0f);
    }
}

// ---------------- fused node MLP + residual (Wz GEMV per node) --------------
__global__ __launch_bounds__(128) void node_kernel(
    const float* __restrict__ Wn1, const float* __restrict__ bn1,
    const float* __restrict__ Wn2, const float* __restrict__ bn2, int layer)
{
    extern __shared__ float sm[];
    float* W1s = sm;                 // 128*64 (Wn1 rows 0..127 only)
    float* W2s = W1s + SD * HID;     // 64*128
    float* Wzs = W2s + HID * SD;     // 64*64
    float* b1s = Wzs + HID * HID;    // 64
    float* b2s = b1s + HID;          // 128
    float* bzs = b2s + SD;           // 64

    const float* W1g = Wn1 + (size_t)layer * 2 * SD * HID;   // first 128 rows
    const float* W2g = Wn2 + (size_t)layer * HID * SD;
    const float* Wzg = g_Wz + (size_t)layer * HID * HID;
    for (int i = threadIdx.x; i < SD * HID; i += 128) W1s[i] = W1g[i];
    for (int i = threadIdx.x; i < HID * SD; i += 128) W2s[i] = W2g[i];
    for (int i = threadIdx.x; i < HID * HID; i += 128) Wzs[i] = Wzg[i];
    if (threadIdx.x < HID) {
        b1s[threadIdx.x] = bn1[layer * HID + threadIdx.x];
        bzs[threadIdx.x] = g_bz[layer * HID + threadIdx.x];
    }
    if (threadIdx.x < SD) b2s[threadIdx.x] = bn2[layer * SD + threadIdx.x];
    __syncthreads();

    int n = blockIdx.x * 128 + threadIdx.x;
    if (n >= N_NODES) return;

    const float4* xs = reinterpret_cast<const float4*>(g_s + (size_t)n * SD);
    float sumC = g_sumC[n];

    // ---- u_pre = s@Wn1a + bn1 ----
    unsigned long long up[32];
    {
        const unsigned long long* bp = (const unsigned long long*)b1s;
#pragma unroll
        for (int q = 0; q < 32; q++) up[q] = bp[q];
    }
#pragma unroll 4
    for (int kk = 0; kk < SD / 4; kk++) {
        float4 xv = xs[kk];
        float xr[4] = {xv.x, xv.y, xv.z, xv.w};
#pragma unroll
        for (int t = 0; t < 4; t++) {
            unsigned long long xk2 = pack2(xr[t]);
            const ulonglong2* wrow = reinterpret_cast<const ulonglong2*>(W1s + (kk * 4 + t) * HID);
#pragma unroll
            for (int q = 0; q < 16; q++) {
                ulonglong2 w = wrow[q];
                fma2(up[2 * q + 0], xk2, w.x);
                fma2(up[2 * q + 1], xk2, w.y);
            }
        }
    }

    // ---- u_pre += h2agg @ Wz ----
    {
        const float4* zp = reinterpret_cast<const float4*>(g_h2agg + (size_t)n * HID);
#pragma unroll 4
        for (int kk = 0; kk < HID / 4; kk++) {
            float4 zv = zp[kk];
            float zr[4] = {zv.x, zv.y, zv.z, zv.w};
#pragma unroll
            for (int t = 0; t < 4; t++) {
                unsigned long long zk2 = pack2(zr[t]);
                const ulonglong2* wrow = reinterpret_cast<const ulonglong2*>(Wzs + (kk * 4 + t) * HID);
#pragma unroll
                for (int q = 0; q < 16; q++) {
                    ulonglong2 w = wrow[q];
                    fma2(up[2 * q + 0], zk2, w.x);
                    fma2(up[2 * q + 1], zk2, w.y);
                }
            }
        }
    }

    float u[HID];
#pragma unroll
    for (int q = 0; q < 32; q++) {
        float lo, hi;
        unpack2(up[q], lo, hi);
        u[2 * q + 0] = silu(lo + sumC * bzs[2 * q + 0]);
        u[2 * q + 1] = silu(hi + sumC * bzs[2 * q + 1]);
    }

    float* sp = g_s + (size_t)n * SD;
#pragma unroll 1
    for (int c = 0; c < 4; c++) {
        unsigned long long acc[16];
        const unsigned long long* bp = (const unsigned long long*)(b2s + c * 32);
#pragma unroll
        for (int q = 0; q < 16; q++) acc[q] = bp[q];
#pragma unroll 4
        for (int k = 0; k < HID; k++) {
            unsigned long long hk2 = pack2(u[k]);
            const ulonglong2* wrow = reinterpret_cast<const ulonglong2*>(W2s + k * SD + c * 32);
#pragma unroll
            for (int q = 0; q < 8; q++) {
                ulonglong2 w = wrow[q];
                fma2(acc[2 * q + 0], hk2, w.x);
                fma2(acc[2 * q + 1], hk2, w.y);
            }
        }
#pragma unroll
        for (int q = 0; q < 16; q++) {
            float lo, hi;
            unpack2(acc[q], lo, hi);
            sp[c * 32 + 2 * q + 0] += lo;
            sp[c * 32 + 2 * q + 1] += hi;
        }
    }

    float inv = g_inv[n];
    float* vp = g_v + (size_t)n * 9;
    const float* va = g_vagg + (size_t)n * 12;
#pragma unroll
    for (int a = 0; a < 3; a++)
#pragma unroll
        for (int j = 0; j < 3; j++)
            vp[a * 3 + j] += va[a * 4 + j] * inv;
}

__global__ void write_out(float* __restrict__ out) {
    int i = blockIdx.x * blockDim.x + threadIdx.x;
    int stride = gridDim.x * blockDim.x;
    for (int k = i; k < N_NODES * SD; k += stride) out[k] = g_s[k];
    for (int k = i; k < N_NODES * VD * 3; k += stride) out[N_NODES * SD + k] = g_v[k];
}

// ---------------- launch ----------------
extern "C" void kernel_launch(void* const* d_in, const int* in_sizes, int n_in,
                              void* d_out, int out_size) {
    const float* s   = (const float*)d_in[0];
    const float* v   = (const float*)d_in[1];
    const int*   ei  = (const int*)d_in[2];
    const float* d   = (const float*)d_in[3];
    const float* r   = (const float*)d_in[4];
    const float* W1  = (const float*)d_in[5];
    const float* b1  = (const float*)d_in[6];
    const float* W2  = (const float*)d_in[7];
    const float* b2  = (const float*)d_in[8];
    const float* W3  = (const float*)d_in[9];
    const float* b3  = (const float*)d_in[10];
    const float* Wn1 = (const float*)d_in[11];
    const float* bn1 = (const float*)d_in[12];
    const float* Wn2 = (const float*)d_in[13];
    const float* bn2 = (const float*)d_in[14];
    float* out = (float*)d_out;

    const int pre_smem  = (256 * HID + HID) * 4;
    const int edge_smem = (HID * HID + HID * 8 + HID + HID + 8) * 4;
    const int node_smem = (SD * HID + HID * SD + HID * HID + HID + SD + HID) * 4;
    cudaFuncSetAttribute(precompute_h, cudaFuncAttributeMaxDynamicSharedMemorySize, pre_smem);
    cudaFuncSetAttribute(edge_kernel, cudaFuncAttributeMaxDynamicSharedMemorySize, edge_smem);
    cudaFuncSetAttribute(node_kernel, cudaFuncAttributeMaxDynamicSharedMemorySize, node_smem);

    init_state<<<1024, 256>>>(s, v);
    prep_edges<<<(N_EDGES + 255) / 256, 256>>>(ei, d);
    compute_inv<<<(N_NODES + 255) / 256, 256>>>();
    fuse_w3_all<<<(DEPTH * (HID * HID + HID) + 255) / 256, 256>>>(W3, Wn1, b3);

    for (int l = 0; l < DEPTH; l++) {
        precompute_h<<<(N_NODES + 127) / 128, 128, pre_smem>>>(W1, b1, l);
        zero_agg<<<1024, 256>>>();
        edge_kernel<<<(N_EDGES + EBLK - 1) / EBLK, EBLK, edge_smem>>>(ei, d, r, W1, W2, b2, W3, b3, l);
        node_kernel<<<(N_NODES + 127) / 128, 128, node_smem>>>(Wn1, bn1, Wn2, bn2, l);
    }
    write_out<<<1024, 256>>>(out);
}